// round 4
// baseline (speedup 1.0000x reference)
#include <cuda_runtime.h>
#include <cuda_bf16.h>
#include <math.h>
#include <stdint.h>

#define HID    512
#define BATCH  4096
#define TSTEPS 20

#define BM 128
#define BN 64

#define SKA 520                       // resident A row stride (bf16 el), pad 8
#define SKB 72                        // staged tile row stride
#define A_SM_BYTES (128 * SKA * 2)    // 133120
#define B_EL       (64 * SKB)         // 4608 el per B tile (64 x 64 bf16 padded)
#define F_BSTAGE_EL (3 * B_EL)        // Wi, Wg, Wo tiles
#define F_SMEM (A_SM_BYTES + 2 * F_BSTAGE_EL * 2)   // 188416 B

#define W_A_EL     (128 * SKB)
#define W_STAGE_EL (W_A_EL + B_EL)
#define W_SMEM     (2 * W_STAGE_EL * 2)              // 55296 B

// ---------------- scratch ----------------------------------------------------
__device__ __align__(16) float          g_zbuf[2][BATCH * HID];
__device__ __align__(16) __nv_bfloat16  g_dhb [BATCH * HID];
__device__ __align__(16) float          g_s   [BATCH * HID];
__device__ __align__(16) __nv_bfloat16  g_wb  [4][HID * HID];  // Wi, Wg, Wo, Wout

// ---------------- helpers ----------------------------------------------------
static __device__ __forceinline__ uint32_t smem_u32(const void* p) {
    uint32_t a;
    asm("{ .reg .u64 t; cvta.to.shared.u64 t, %1; cvt.u32.u64 %0, t; }" : "=r"(a) : "l"(p));
    return a;
}
#define CP16(dst, src) \
    asm volatile("cp.async.cg.shared.global [%0], [%1], 16;" :: "r"(dst), "l"(src))
#define CPC()  asm volatile("cp.async.commit_group;" ::: "memory")
#define CPW1() asm volatile("cp.async.wait_group 1;" ::: "memory")
#define CPW0() asm volatile("cp.async.wait_group 0;" ::: "memory")

__device__ __forceinline__ void ldm4(uint32_t a, uint32_t& r0, uint32_t& r1,
                                     uint32_t& r2, uint32_t& r3) {
    asm volatile("ldmatrix.sync.aligned.m8n8.x4.shared.b16 {%0,%1,%2,%3}, [%4];"
                 : "=r"(r0), "=r"(r1), "=r"(r2), "=r"(r3) : "r"(a));
}
__device__ __forceinline__ void mma16816(float* c, const uint32_t* a, uint32_t b0, uint32_t b1) {
    asm volatile("mma.sync.aligned.m16n8k16.row.col.f32.bf16.bf16.f32 "
                 "{%0,%1,%2,%3},{%4,%5,%6,%7},{%8,%9},{%0,%1,%2,%3};"
                 : "+f"(c[0]), "+f"(c[1]), "+f"(c[2]), "+f"(c[3])
                 : "r"(a[0]), "r"(a[1]), "r"(a[2]), "r"(a[3]), "r"(b0), "r"(b1));
}
__device__ __forceinline__ float fsig(float x)  { return __fdividef(1.f, 1.f + __expf(-x)); }
__device__ __forceinline__ float ftanh(float x) { return __fdividef(2.f, 1.f + __expf(-2.f * x)) - 1.f; }
__device__ __forceinline__ float wmax(float v) {
    #pragma unroll
    for (int o = 16; o; o >>= 1) v = fmaxf(v, __shfl_xor_sync(0xffffffffu, v, o));
    return v;
}
__device__ __forceinline__ float wsum(float v) {
    #pragma unroll
    for (int o = 16; o; o >>= 1) v += __shfl_xor_sync(0xffffffffu, v, o);
    return v;
}

__device__ __forceinline__ void mma_block(float acc[2][4][4],
                                          const uint32_t fa[2][4], const uint32_t fb[2][4]) {
    #pragma unroll
    for (int mi = 0; mi < 2; ++mi) {
        mma16816(acc[mi][0], fa[mi], fb[0][0], fb[0][1]);
        mma16816(acc[mi][1], fa[mi], fb[0][2], fb[0][3]);
        mma16816(acc[mi][2], fa[mi], fb[1][0], fb[1][1]);
        mma16816(acc[mi][3], fa[mi], fb[1][2], fb[1][3]);
    }
}

// ---------------- setup ------------------------------------------------------
__global__ void w2bf_kernel(const float* __restrict__ Wi, const float* __restrict__ Wg,
                            const float* __restrict__ Wo, const float* __restrict__ Wout) {
    int i = blockIdx.x * blockDim.x + threadIdx.x;
    if (i >= 4 * HID * HID) return;
    int m = i >> 18, r = i & (HID * HID - 1);
    const float* src = (m == 0) ? Wi : (m == 1) ? Wg : (m == 2) ? Wo : Wout;
    g_wb[m][r] = __float2bfloat16_rn(src[r]);
}

// ---------------- cp.async issuers -------------------------------------------
__device__ __forceinline__ void fb_issue(uint32_t sA, int tid, int bn, int ch) {
    const uint32_t bb = sA + A_SM_BYTES + (uint32_t)(ch & 1) * (F_BSTAGE_EL * 2);
    const int k0 = ch * 64;
    #pragma unroll
    for (int i = 0; i < 6; ++i) {
        int idx = i * 256 + tid;                 // 0..1535
        int w = idx >> 9, r = (idx >> 3) & 63, c = idx & 7;
        uint32_t dst = bb + (uint32_t)(w * B_EL + r * SKB + c * 8) * 2;
        const __nv_bfloat16* src = g_wb[w] + (bn + r) * HID + k0 + c * 8;
        CP16(dst, src);
    }
    CPC();
}
__device__ __forceinline__ void w_issue(uint32_t sb, int tid, int bm, int bn, int ch) {
    const uint32_t base = sb + (uint32_t)(ch & 1) * (W_STAGE_EL * 2);
    const int k0 = ch * 64;
    #pragma unroll
    for (int i = 0; i < 6; ++i) {
        int idx = i * 256 + tid;                 // 0..1535
        uint32_t dst; const __nv_bfloat16* src;
        if (idx < 1024) {
            int r = idx >> 3, c = idx & 7;
            dst = base + (uint32_t)(r * SKB + c * 8) * 2;
            src = g_dhb + (bm + r) * HID + k0 + c * 8;
        } else {
            int ib = idx - 1024;
            int r = ib >> 3, c = ib & 7;
            dst = base + (uint32_t)(W_A_EL + r * SKB + c * 8) * 2;
            src = g_wb[3] + (bn + r) * HID + k0 + c * 8;
        }
        CP16(dst, src);
    }
    CPC();
}

// ---------------- fused step: z-update + readout + i/g/o GEMM ----------------
// For t>0: z_t = z_{t-1} + dt*softmax(s);  out[:,t] = softmax(z_t).Wfc + bfc
// Then dh = sig(z@Wo^T) * tanh( sig(z@Wi^T) * tanh(z@Wg^T) ) -> g_dhb
__global__ __launch_bounds__(256, 1) void fused_step(
    const float* __restrict__ y, const float* __restrict__ ts,
    const float* __restrict__ Wfc, const float* __restrict__ bfc,
    float* __restrict__ out, int t)
{
    extern __shared__ __nv_bfloat16 sm[];
    const uint32_t sA = smem_u32(sm);
    const int tid = threadIdx.x, lane = tid & 31, wid = tid >> 5;
    const int warpM = wid & 3, warpN = wid >> 2;
    const int bm = blockIdx.x * BM, bn = blockIdx.y * BN;
    const bool writer = (blockIdx.y == 0);

    // start B prefetch for chunks 0,1 immediately (overlaps prologue)
    fb_issue(sA, tid, bn, 0);
    fb_issue(sA, tid, bn, 1);

    // ---- prologue: z update + smem-A fill + readout ----
    const float* zsrc = (t <= 1) ? y : (const float*)g_zbuf[(t - 1) & 1];
    float* zdst = g_zbuf[t & 1];
    const float dt = (t > 0) ? (ts[t] - ts[t - 1]) : 0.f;

    float wv[16]; float bfc0 = 0.f;
    if (writer) {
        #pragma unroll
        for (int q = 0; q < 4; ++q) {
            float4 f = *(const float4*)(Wfc + lane * 16 + q * 4);
            wv[q * 4] = f.x; wv[q * 4 + 1] = f.y; wv[q * 4 + 2] = f.z; wv[q * 4 + 3] = f.w;
        }
        bfc0 = bfc[0];
    }

    #pragma unroll 1
    for (int rr = 0; rr < 16; ++rr) {
        const int r = wid * 16 + rr, grow = bm + r;
        float zv[16];
        #pragma unroll
        for (int q = 0; q < 4; ++q)
            *(float4*)&zv[q * 4] = *(const float4*)(zsrc + grow * HID + lane * 16 + q * 4);
        if (t > 0) {
            float sv[16];
            #pragma unroll
            for (int q = 0; q < 4; ++q)
                *(float4*)&sv[q * 4] = *(const float4*)(g_s + grow * HID + lane * 16 + q * 4);
            float mx = sv[0];
            #pragma unroll
            for (int j = 1; j < 16; ++j) mx = fmaxf(mx, sv[j]);
            mx = wmax(mx);
            float se = 0.f;
            #pragma unroll
            for (int j = 0; j < 16; ++j) { sv[j] = __expf(sv[j] - mx); se += sv[j]; }
            se = wsum(se);
            float sc = __fdividef(dt, se);
            #pragma unroll
            for (int j = 0; j < 16; ++j) zv[j] = fmaf(sv[j], sc, zv[j]);
            if (writer) {
                #pragma unroll
                for (int q = 0; q < 4; ++q)
                    *(float4*)(zdst + grow * HID + lane * 16 + q * 4) = *(float4*)&zv[q * 4];
            }
        }
        // fill resident A tile (bf16)
        uint32_t pk[8];
        #pragma unroll
        for (int j = 0; j < 8; ++j) {
            __nv_bfloat162 h = __floats2bfloat162_rn(zv[2 * j], zv[2 * j + 1]);
            pk[j] = *(uint32_t*)&h;
        }
        uint32_t adst = sA + (uint32_t)(r * SKA + lane * 16) * 2;
        asm volatile("st.shared.v4.b32 [%0], {%1,%2,%3,%4};"
                     :: "r"(adst), "r"(pk[0]), "r"(pk[1]), "r"(pk[2]), "r"(pk[3]) : "memory");
        asm volatile("st.shared.v4.b32 [%0], {%1,%2,%3,%4};"
                     :: "r"(adst + 16), "r"(pk[4]), "r"(pk[5]), "r"(pk[6]), "r"(pk[7]) : "memory");
        if (writer) {
            float mx2 = zv[0];
            #pragma unroll
            for (int j = 1; j < 16; ++j) mx2 = fmaxf(mx2, zv[j]);
            mx2 = wmax(mx2);
            float se2 = 0.f, dot = 0.f;
            #pragma unroll
            for (int j = 0; j < 16; ++j) {
                float e = __expf(zv[j] - mx2);
                se2 += e; dot = fmaf(e, wv[j], dot);
            }
            se2 = wsum(se2); dot = wsum(dot);
            if (lane == 0) out[grow * TSTEPS + t] = __fdividef(dot, se2) + bfc0;
        }
    }
    __syncthreads();

    // ---- GEMM mainloop ----
    float ai[2][4][4], ag[2][4][4], ao[2][4][4];
    #pragma unroll
    for (int x = 0; x < 2; ++x)
        #pragma unroll
        for (int yq = 0; yq < 4; ++yq)
            #pragma unroll
            for (int zq = 0; zq < 4; ++zq) { ai[x][yq][zq] = 0.f; ag[x][yq][zq] = 0.f; ao[x][yq][zq] = 0.f; }

    const int am = warpM * 32 + (lane & 15);
    const int ak = (lane >> 4) << 3;
    const int bnrow = warpN * 32 + ((lane >> 4) << 3) + (lane & 7);
    const int bk = ((lane >> 3) & 1) << 3;

    uint32_t fa[2][2][4], fbI[2][2][4], fbG[2][2][4], fbO[2][2][4];

    for (int ch = 0; ch < 8; ++ch) {
        if (ch < 7) { CPW1(); } else { CPW0(); }
        __syncthreads();
        const uint32_t bb = sA + A_SM_BYTES + (uint32_t)(ch & 1) * (F_BSTAGE_EL * 2);
        const uint32_t bI = bb, bG = bb + B_EL * 2, bO = bb + 2 * B_EL * 2;
        const int kg = ch * 64;

        #define LOADF(B, KK) do {                                                         \
            uint32_t aadr = sA + (uint32_t)(am * SKA + kg + (KK) + ak) * 2;               \
            ldm4(aadr,                fa[B][0][0], fa[B][0][1], fa[B][0][2], fa[B][0][3]);\
            ldm4(aadr + 16 * SKA * 2, fa[B][1][0], fa[B][1][1], fa[B][1][2], fa[B][1][3]);\
            uint32_t o0 = (uint32_t)(bnrow * SKB + bk + (KK)) * 2;                        \
            uint32_t o1 = o0 + 16 * SKB * 2;                                              \
            ldm4(bI + o0, fbI[B][0][0], fbI[B][0][1], fbI[B][0][2], fbI[B][0][3]);        \
            ldm4(bI + o1, fbI[B][1][0], fbI[B][1][1], fbI[B][1][2], fbI[B][1][3]);        \
            ldm4(bG + o0, fbG[B][0][0], fbG[B][0][1], fbG[B][0][2], fbG[B][0][3]);        \
            ldm4(bG + o1, fbG[B][1][0], fbG[B][1][1], fbG[B][1][2], fbG[B][1][3]);        \
            ldm4(bO + o0, fbO[B][0][0], fbO[B][0][1], fbO[B][0][2], fbO[B][0][3]);        \
            ldm4(bO + o1, fbO[B][1][0], fbO[B][1][1], fbO[B][1][2], fbO[B][1][3]);        \
        } while (0)

        LOADF(0, 0);
        #pragma unroll
        for (int s4 = 0; s4 < 4; ++s4) {
            const int cur = s4 & 1, nxt = cur ^ 1;
            if (s4 == 0) LOADF(1, 16);
            if (s4 == 1) LOADF(0, 32);
            if (s4 == 2) LOADF(1, 48);
            mma_block(ai, fa[cur], fbI[cur]);
            mma_block(ag, fa[cur], fbG[cur]);
            mma_block(ao, fa[cur], fbO[cur]);
            (void)nxt;
        }
        #undef LOADF
        __syncthreads();
        if (ch < 6) fb_issue(sA, tid, bn, ch + 2);
    }

    // ---- epilogue: dh activation -> g_dhb ----
    #pragma unroll
    for (int mi = 0; mi < 2; ++mi) {
        const int r = bm + warpM * 32 + mi * 16 + (lane >> 2);
        #pragma unroll
        for (int ni = 0; ni < 4; ++ni) {
            const int col = bn + warpN * 32 + ni * 8 + ((lane & 3) << 1);
            float I0 = fsig(ai[mi][ni][0]), G0 = ftanh(ag[mi][ni][0]), O0 = fsig(ao[mi][ni][0]);
            float I1 = fsig(ai[mi][ni][1]), G1 = ftanh(ag[mi][ni][1]), O1 = fsig(ao[mi][ni][1]);
            float I2 = fsig(ai[mi][ni][2]), G2 = ftanh(ag[mi][ni][2]), O2 = fsig(ao[mi][ni][2]);
            float I3 = fsig(ai[mi][ni][3]), G3 = ftanh(ag[mi][ni][3]), O3 = fsig(ao[mi][ni][3]);
            *(__nv_bfloat162*)(g_dhb + r * HID + col) =
                __floats2bfloat162_rn(O0 * ftanh(I0 * G0), O1 * ftanh(I1 * G1));
            *(__nv_bfloat162*)(g_dhb + (r + 8) * HID + col) =
                __floats2bfloat162_rn(O2 * ftanh(I2 * G2), O3 * ftanh(I3 * G3));
        }
    }
}

// ---------------- Wout GEMM: s = dh @ Wout^T + bout --------------------------
__global__ __launch_bounds__(256, 2) void wout_mma(const float* __restrict__ bout) {
    extern __shared__ __nv_bfloat16 sm[];
    const uint32_t sb = smem_u32(sm);
    const int tid = threadIdx.x, lane = tid & 31;
    const int warpM = (tid >> 5) & 3, warpN = tid >> 7;
    const int bm = blockIdx.x * BM, bn = blockIdx.y * BN;

    float acc[2][4][4];
    #pragma unroll
    for (int x = 0; x < 2; ++x)
        #pragma unroll
        for (int yq = 0; yq < 4; ++yq)
            #pragma unroll
            for (int zq = 0; zq < 4; ++zq) acc[x][yq][zq] = 0.f;

    const int am = warpM * 32 + (lane & 15);
    const int ak = (lane >> 4) << 3;
    const int bnrow = warpN * 32 + ((lane >> 4) << 3) + (lane & 7);
    const int bk = ((lane >> 3) & 1) << 3;

    uint32_t fa[2][2][4], fb[2][2][4];

    w_issue(sb, tid, bm, bn, 0);
    w_issue(sb, tid, bm, bn, 1);

    for (int ch = 0; ch < 8; ++ch) {
        if (ch < 7) { CPW1(); } else { CPW0(); }
        __syncthreads();
        const uint32_t base  = sb + (uint32_t)(ch & 1) * (W_STAGE_EL * 2);
        const uint32_t baseB = base + W_A_EL * 2;

        #define LOADW(B, KK) do {                                                         \
            uint32_t aadr = base + (uint32_t)(am * SKB + (KK) + ak) * 2;                  \
            ldm4(aadr,                fa[B][0][0], fa[B][0][1], fa[B][0][2], fa[B][0][3]);\
            ldm4(aadr + 16 * SKB * 2, fa[B][1][0], fa[B][1][1], fa[B][1][2], fa[B][1][3]);\
            uint32_t o0 = baseB + (uint32_t)(bnrow * SKB + bk + (KK)) * 2;                \
            uint32_t o1 = o0 + 16 * SKB * 2;                                              \
            ldm4(o0, fb[B][0][0], fb[B][0][1], fb[B][0][2], fb[B][0][3]);                 \
            ldm4(o1, fb[B][1][0], fb[B][1][1], fb[B][1][2], fb[B][1][3]);                 \
        } while (0)

        LOADW(0, 0);
        #pragma unroll
        for (int s4 = 0; s4 < 4; ++s4) {
            const int cur = s4 & 1;
            if (s4 == 0) LOADW(1, 16);
            if (s4 == 1) LOADW(0, 32);
            if (s4 == 2) LOADW(1, 48);
            mma_block(acc, fa[cur], fb[cur]);
        }
        #undef LOADW
        __syncthreads();
        if (ch < 6) w_issue(sb, tid, bm, bn, ch + 2);
    }

    #pragma unroll
    for (int mi = 0; mi < 2; ++mi) {
        const int r = bm + warpM * 32 + mi * 16 + (lane >> 2);
        #pragma unroll
        for (int ni = 0; ni < 4; ++ni) {
            const int col = bn + warpN * 32 + ni * 8 + ((lane & 3) << 1);
            float b0v = bout[col], b1v = bout[col + 1];
            float2 lo = { acc[mi][ni][0] + b0v, acc[mi][ni][1] + b1v };
            float2 hi = { acc[mi][ni][2] + b0v, acc[mi][ni][3] + b1v };
            *(float2*)(g_s + r * HID + col)       = lo;
            *(float2*)(g_s + (r + 8) * HID + col) = hi;
        }
    }
}

// ---------------- final step: z_19 + out[:,19] --------------------------------
__global__ __launch_bounds__(256) void final_out_kernel(
    const float* __restrict__ ts, const float* __restrict__ Wfc,
    const float* __restrict__ bfc, float* __restrict__ out)
{
    const int b = blockIdx.x;
    const int tid = threadIdx.x;
    __shared__ float red_a[8], red_b[8];

    float v0 = g_s[b * HID + tid], v1 = g_s[b * HID + tid + 256];
    float m = fmaxf(v0, v1);
    #pragma unroll
    for (int o = 16; o; o >>= 1) m = fmaxf(m, __shfl_xor_sync(0xffffffffu, m, o));
    if ((tid & 31) == 0) red_a[tid >> 5] = m;
    __syncthreads();
    if (tid == 0) {
        float mm = red_a[0];
        #pragma unroll
        for (int i = 1; i < 8; ++i) mm = fmaxf(mm, red_a[i]);
        red_a[0] = mm;
    }
    __syncthreads();
    m = red_a[0];
    __syncthreads();
    float e0 = __expf(v0 - m), e1 = __expf(v1 - m);
    float s = e0 + e1;
    #pragma unroll
    for (int o = 16; o; o >>= 1) s += __shfl_xor_sync(0xffffffffu, s, o);
    if ((tid & 31) == 0) red_a[tid >> 5] = s;
    __syncthreads();
    if (tid == 0) {
        float ss = 0.f;
        #pragma unroll
        for (int i = 0; i < 8; ++i) ss += red_a[i];
        red_a[0] = ss;
    }
    __syncthreads();
    float dt = ts[TSTEPS - 1] - ts[TSTEPS - 2];
    float inv = __fdividef(dt, red_a[0]);
    // z_18 lives in g_zbuf[0] (written at t=18)
    float z0 = g_zbuf[0][b * HID + tid      ] + e0 * inv;
    float z1 = g_zbuf[0][b * HID + tid + 256] + e1 * inv;
    __syncthreads();

    m = fmaxf(z0, z1);
    #pragma unroll
    for (int o = 16; o; o >>= 1) m = fmaxf(m, __shfl_xor_sync(0xffffffffu, m, o));
    if ((tid & 31) == 0) red_a[tid >> 5] = m;
    __syncthreads();
    if (tid == 0) {
        float mm = red_a[0];
        #pragma unroll
        for (int i = 1; i < 8; ++i) mm = fmaxf(mm, red_a[i]);
        red_a[0] = mm;
    }
    __syncthreads();
    m = red_a[0];
    __syncthreads();
    e0 = __expf(z0 - m); e1 = __expf(z1 - m);
    s = e0 + e1;
    float d = e0 * Wfc[tid] + e1 * Wfc[tid + 256];
    #pragma unroll
    for (int o = 16; o; o >>= 1) {
        s += __shfl_xor_sync(0xffffffffu, s, o);
        d += __shfl_xor_sync(0xffffffffu, d, o);
    }
    if ((tid & 31) == 0) { red_a[tid >> 5] = s; red_b[tid >> 5] = d; }
    __syncthreads();
    if (tid == 0) {
        float ss = 0.f, dd = 0.f;
        #pragma unroll
        for (int i = 0; i < 8; ++i) { ss += red_a[i]; dd += red_b[i]; }
        out[b * TSTEPS + TSTEPS - 1] = __fdividef(dd, ss) + bfc[0];
    }
}

// ---------------- launch -----------------------------------------------------
extern "C" void kernel_launch(void* const* d_in, const int* in_sizes, int n_in,
                              void* d_out, int out_size) {
    const float* y    = (const float*)d_in[0];
    const float* ts   = (const float*)d_in[1];
    const float* Wi   = (const float*)d_in[2];
    // d_in[3] = Wf — dead in the reference (f computed but unused), skipped.
    const float* Wg   = (const float*)d_in[4];
    const float* Wo   = (const float*)d_in[5];
    const float* Wout = (const float*)d_in[6];
    const float* bout = (const float*)d_in[7];
    const float* Wfc  = (const float*)d_in[8];
    const float* bfc  = (const float*)d_in[9];
    float* out = (float*)d_out;

    cudaFuncSetAttribute(fused_step, cudaFuncAttributeMaxDynamicSharedMemorySize, F_SMEM);
    cudaFuncSetAttribute(wout_mma,   cudaFuncAttributeMaxDynamicSharedMemorySize, W_SMEM);

    w2bf_kernel<<<(4 * HID * HID + 255) / 256, 256>>>(Wi, Wg, Wo, Wout);

    dim3 ggrid(BATCH / BM, HID / BN);
    for (int t = 0; t < TSTEPS - 1; ++t) {
        fused_step<<<ggrid, 256, F_SMEM>>>(y, ts, Wfc, bfc, out, t);
        wout_mma<<<ggrid, 256, W_SMEM>>>(bout);
    }
    final_out_kernel<<<BATCH, 256>>>(ts, Wfc, bfc, out);
}

// round 5
// speedup vs baseline: 1.1576x; 1.1576x over previous
#include <cuda_runtime.h>
#include <cuda_bf16.h>
#include <math.h>
#include <stdint.h>

#define HID    512
#define BATCH  4096
#define TSTEPS 20

#define BM 64
#define BN 64
#define BK 64
#define SK 72                           // padded smem row stride (bf16)
#define TILE_EL (64 * SK)               // 4608 el per 64x64 tile
#define F_STAGE_EL (4 * TILE_EL)        // A + Wi + Wg + Wo
#define F_SMEM (2 * F_STAGE_EL * 2)     // 73728 B
#define W_STAGE_EL (2 * TILE_EL)
#define W_SMEM (2 * W_STAGE_EL * 2)     // 36864 B

// ---------------- scratch ----------------------------------------------------
__device__ __align__(16) float          g_z  [BATCH * HID];
__device__ __align__(16) __nv_bfloat16  g_zb [BATCH * HID];
__device__ __align__(16) __nv_bfloat16  g_dhb[BATCH * HID];
__device__ __align__(16) float          g_s  [BATCH * HID];
__device__ __align__(16) __nv_bfloat16  g_wb [4][HID * HID];   // Wi, Wg, Wo, Wout

// ---------------- helpers ----------------------------------------------------
static __device__ __forceinline__ uint32_t smem_u32(const void* p) {
    uint32_t a;
    asm("{ .reg .u64 t; cvta.to.shared.u64 t, %1; cvt.u32.u64 %0, t; }" : "=r"(a) : "l"(p));
    return a;
}
#define CP16(dst, src) \
    asm volatile("cp.async.cg.shared.global [%0], [%1], 16;" :: "r"(dst), "l"(src))
#define CPC()  asm volatile("cp.async.commit_group;" ::: "memory")
#define CPW1() asm volatile("cp.async.wait_group 1;" ::: "memory")
#define CPW0() asm volatile("cp.async.wait_group 0;" ::: "memory")

__device__ __forceinline__ void ldm4(uint32_t a, uint32_t& r0, uint32_t& r1,
                                     uint32_t& r2, uint32_t& r3) {
    asm volatile("ldmatrix.sync.aligned.m8n8.x4.shared.b16 {%0,%1,%2,%3}, [%4];"
                 : "=r"(r0), "=r"(r1), "=r"(r2), "=r"(r3) : "r"(a));
}
__device__ __forceinline__ void mma16816(float* c, const uint32_t* a, uint32_t b0, uint32_t b1) {
    asm volatile("mma.sync.aligned.m16n8k16.row.col.f32.bf16.bf16.f32 "
                 "{%0,%1,%2,%3},{%4,%5,%6,%7},{%8,%9},{%0,%1,%2,%3};"
                 : "+f"(c[0]), "+f"(c[1]), "+f"(c[2]), "+f"(c[3])
                 : "r"(a[0]), "r"(a[1]), "r"(a[2]), "r"(a[3]), "r"(b0), "r"(b1));
}
__device__ __forceinline__ float fsig(float x)  { return __fdividef(1.f, 1.f + __expf(-x)); }
__device__ __forceinline__ float ftanh(float x) { return __fdividef(2.f, 1.f + __expf(-2.f * x)) - 1.f; }

// ---------------- setup ------------------------------------------------------
__global__ void w2bf_kernel(const float* __restrict__ Wi, const float* __restrict__ Wg,
                            const float* __restrict__ Wo, const float* __restrict__ Wout) {
    int i = blockIdx.x * blockDim.x + threadIdx.x;
    if (i >= 4 * HID * HID) return;
    int m = i >> 18, r = i & (HID * HID - 1);
    const float* src = (m == 0) ? Wi : (m == 1) ? Wg : (m == 2) ? Wo : Wout;
    g_wb[m][r] = __float2bfloat16_rn(src[r]);
}

__global__ void copy_z_kernel(const float* __restrict__ y) {
    int i = blockIdx.x * blockDim.x + threadIdx.x;
    if (i < BATCH * HID) { float v = y[i]; g_z[i] = v; g_zb[i] = __float2bfloat16_rn(v); }
}

// ---------------- cp.async issuers -------------------------------------------
__device__ __forceinline__ void f_issue(uint32_t sb, int tid, int bm, int bn, int ch) {
    const uint32_t base = sb + (uint32_t)(ch & 1) * (F_STAGE_EL * 2);
    const int k0 = ch * BK;
    #pragma unroll
    for (int i = 0; i < 8; ++i) {
        int idx = i * 256 + tid;              // 0..2047
        int tl = idx >> 9, r = (idx >> 3) & 63, c = idx & 7;
        const __nv_bfloat16* src = (tl == 0)
            ? (g_zb + (bm + r) * HID + k0 + c * 8)
            : (g_wb[tl - 1] + (bn + r) * HID + k0 + c * 8);
        uint32_t dst = base + (uint32_t)(tl * TILE_EL + r * SK + c * 8) * 2;
        CP16(dst, src);
    }
    CPC();
}
__device__ __forceinline__ void w_issue(uint32_t sb, int tid, int bm, int bn, int ch) {
    const uint32_t base = sb + (uint32_t)(ch & 1) * (W_STAGE_EL * 2);
    const int k0 = ch * BK;
    #pragma unroll
    for (int i = 0; i < 4; ++i) {
        int idx = i * 256 + tid;              // 0..1023
        int tl = idx >> 9, r = (idx >> 3) & 63, c = idx & 7;
        const __nv_bfloat16* src = (tl == 0)
            ? (g_dhb + (bm + r) * HID + k0 + c * 8)
            : (g_wb[3] + (bn + r) * HID + k0 + c * 8);
        uint32_t dst = base + (uint32_t)(tl * TILE_EL + r * SK + c * 8) * 2;
        CP16(dst, src);
    }
    CPC();
}

// ---------------- fused i/g/o HMMA GEMM (64x64 tile, occ 2) ------------------
// dh = sig(z@Wo^T) * tanh( sig(z@Wi^T) * tanh(z@Wg^T) ) -> g_dhb (bf16)
__global__ __launch_bounds__(256, 2) void fused_igo_mma() {
    extern __shared__ __nv_bfloat16 sm[];
    const uint32_t sb = smem_u32(sm);
    const int tid = threadIdx.x, lane = tid & 31, wid = tid >> 5;
    const int warpM = wid & 1, warpN = wid >> 1;      // 2 x 4 warps
    const int bm = blockIdx.x * BM, bn = blockIdx.y * BN;

    float acc[3][2][2][4];                            // [weight][mi][ni][4]
    #pragma unroll
    for (int w = 0; w < 3; ++w)
        #pragma unroll
        for (int mi = 0; mi < 2; ++mi)
            #pragma unroll
            for (int ni = 0; ni < 2; ++ni)
                #pragma unroll
                for (int q = 0; q < 4; ++q) acc[w][mi][ni][q] = 0.f;

    const int am = warpM * 32 + (lane & 15);
    const int ak = (lane >> 4) << 3;
    const int bnrow = warpN * 16 + ((lane >> 4) << 3) + (lane & 7);
    const int bk = ((lane >> 3) & 1) << 3;

    f_issue(sb, tid, bm, bn, 0);
    f_issue(sb, tid, bm, bn, 1);

    for (int ch = 0; ch < HID / BK; ++ch) {
        if (ch < HID / BK - 1) { CPW1(); } else { CPW0(); }
        __syncthreads();
        const uint32_t base = sb + (uint32_t)(ch & 1) * (F_STAGE_EL * 2);
        #pragma unroll
        for (int kk = 0; kk < BK; kk += 16) {
            uint32_t fa[2][4];
            uint32_t aadr = base + (uint32_t)(am * SK + kk + ak) * 2;
            ldm4(aadr,               fa[0][0], fa[0][1], fa[0][2], fa[0][3]);
            ldm4(aadr + 16 * SK * 2, fa[1][0], fa[1][1], fa[1][2], fa[1][3]);
            const uint32_t boff = (uint32_t)(bnrow * SK + kk + bk) * 2;
            #pragma unroll
            for (int w = 0; w < 3; ++w) {
                uint32_t b0, b1, b2, b3;
                ldm4(base + (uint32_t)((w + 1) * TILE_EL) * 2 + boff, b0, b1, b2, b3);
                mma16816(acc[w][0][0], fa[0], b0, b1);
                mma16816(acc[w][0][1], fa[0], b2, b3);
                mma16816(acc[w][1][0], fa[1], b0, b1);
                mma16816(acc[w][1][1], fa[1], b2, b3);
            }
        }
        __syncthreads();
        if (ch < HID / BK - 2) f_issue(sb, tid, bm, bn, ch + 2);
    }

    // epilogue: dh activation -> g_dhb
    #pragma unroll
    for (int mi = 0; mi < 2; ++mi) {
        const int r = bm + warpM * 32 + mi * 16 + (lane >> 2);
        #pragma unroll
        for (int ni = 0; ni < 2; ++ni) {
            const int col = bn + warpN * 16 + ni * 8 + ((lane & 3) << 1);
            float I0 = fsig(acc[0][mi][ni][0]), G0 = ftanh(acc[1][mi][ni][0]), O0 = fsig(acc[2][mi][ni][0]);
            float I1 = fsig(acc[0][mi][ni][1]), G1 = ftanh(acc[1][mi][ni][1]), O1 = fsig(acc[2][mi][ni][1]);
            float I2 = fsig(acc[0][mi][ni][2]), G2 = ftanh(acc[1][mi][ni][2]), O2 = fsig(acc[2][mi][ni][2]);
            float I3 = fsig(acc[0][mi][ni][3]), G3 = ftanh(acc[1][mi][ni][3]), O3 = fsig(acc[2][mi][ni][3]);
            *(__nv_bfloat162*)(g_dhb + r * HID + col) =
                __floats2bfloat162_rn(O0 * ftanh(I0 * G0), O1 * ftanh(I1 * G1));
            *(__nv_bfloat162*)(g_dhb + (r + 8) * HID + col) =
                __floats2bfloat162_rn(O2 * ftanh(I2 * G2), O3 * ftanh(I3 * G3));
        }
    }
}

// ---------------- Wout HMMA GEMM: s = dh @ Wout^T + bout ---------------------
__global__ __launch_bounds__(256, 3) void wout_mma(const float* __restrict__ bout) {
    extern __shared__ __nv_bfloat16 sm[];
    const uint32_t sb = smem_u32(sm);
    const int tid = threadIdx.x, lane = tid & 31, wid = tid >> 5;
    const int warpM = wid & 1, warpN = wid >> 1;
    const int bm = blockIdx.x * BM, bn = blockIdx.y * BN;

    float acc[2][2][4];
    #pragma unroll
    for (int mi = 0; mi < 2; ++mi)
        #pragma unroll
        for (int ni = 0; ni < 2; ++ni)
            #pragma unroll
            for (int q = 0; q < 4; ++q) acc[mi][ni][q] = 0.f;

    const int am = warpM * 32 + (lane & 15);
    const int ak = (lane >> 4) << 3;
    const int bnrow = warpN * 16 + ((lane >> 4) << 3) + (lane & 7);
    const int bk = ((lane >> 3) & 1) << 3;

    w_issue(sb, tid, bm, bn, 0);
    w_issue(sb, tid, bm, bn, 1);

    for (int ch = 0; ch < HID / BK; ++ch) {
        if (ch < HID / BK - 1) { CPW1(); } else { CPW0(); }
        __syncthreads();
        const uint32_t base = sb + (uint32_t)(ch & 1) * (W_STAGE_EL * 2);
        #pragma unroll
        for (int kk = 0; kk < BK; kk += 16) {
            uint32_t fa[2][4], b0, b1, b2, b3;
            uint32_t aadr = base + (uint32_t)(am * SK + kk + ak) * 2;
            ldm4(aadr,               fa[0][0], fa[0][1], fa[0][2], fa[0][3]);
            ldm4(aadr + 16 * SK * 2, fa[1][0], fa[1][1], fa[1][2], fa[1][3]);
            ldm4(base + (uint32_t)(TILE_EL) * 2 + (uint32_t)(bnrow * SK + kk + bk) * 2,
                 b0, b1, b2, b3);
            mma16816(acc[0][0], fa[0], b0, b1);
            mma16816(acc[0][1], fa[0], b2, b3);
            mma16816(acc[1][0], fa[1], b0, b1);
            mma16816(acc[1][1], fa[1], b2, b3);
        }
        __syncthreads();
        if (ch < HID / BK - 2) w_issue(sb, tid, bm, bn, ch + 2);
    }

    #pragma unroll
    for (int mi = 0; mi < 2; ++mi) {
        const int r = bm + warpM * 32 + mi * 16 + (lane >> 2);
        #pragma unroll
        for (int ni = 0; ni < 2; ++ni) {
            const int col = bn + warpN * 16 + ni * 8 + ((lane & 3) << 1);
            float b0v = bout[col], b1v = bout[col + 1];
            float2 lo = { acc[mi][ni][0] + b0v, acc[mi][ni][1] + b1v };
            float2 hi = { acc[mi][ni][2] + b0v, acc[mi][ni][3] + b1v };
            *(float2*)(g_s + r * HID + col)       = lo;
            *(float2*)(g_s + (r + 8) * HID + col) = hi;
        }
    }
}

// ---------------- fused softmax(s)->z update + softmax(z)->out[t+1] ----------
__global__ __launch_bounds__(256) void update_out_kernel(
    const float* __restrict__ ts, const float* __restrict__ Wfc,
    const float* __restrict__ bfc, float* __restrict__ out, int t)
{
    const int b = blockIdx.x;
    const int tid = threadIdx.x;
    __shared__ float red_a[8], red_b[8];

    float v0 = g_s[b * HID + tid], v1 = g_s[b * HID + tid + 256];
    float m = fmaxf(v0, v1);
    #pragma unroll
    for (int o = 16; o; o >>= 1) m = fmaxf(m, __shfl_xor_sync(0xffffffffu, m, o));
    if ((tid & 31) == 0) red_a[tid >> 5] = m;
    __syncthreads();
    if (tid == 0) {
        float mm = red_a[0];
        #pragma unroll
        for (int i = 1; i < 8; ++i) mm = fmaxf(mm, red_a[i]);
        red_a[0] = mm;
    }
    __syncthreads();
    m = red_a[0];
    __syncthreads();
    float e0 = __expf(v0 - m), e1 = __expf(v1 - m);
    float s = e0 + e1;
    #pragma unroll
    for (int o = 16; o; o >>= 1) s += __shfl_xor_sync(0xffffffffu, s, o);
    if ((tid & 31) == 0) red_a[tid >> 5] = s;
    __syncthreads();
    if (tid == 0) {
        float ss = 0.f;
        #pragma unroll
        for (int i = 0; i < 8; ++i) ss += red_a[i];
        red_a[0] = ss;
    }
    __syncthreads();
    float dt = ts[t + 1] - ts[t];
    float inv = __fdividef(dt, red_a[0]);
    float z0 = g_z[b * HID + tid      ] + e0 * inv;
    float z1 = g_z[b * HID + tid + 256] + e1 * inv;
    g_z[b * HID + tid      ] = z0;
    g_z[b * HID + tid + 256] = z1;
    g_zb[b * HID + tid      ] = __float2bfloat16_rn(z0);
    g_zb[b * HID + tid + 256] = __float2bfloat16_rn(z1);
    __syncthreads();

    m = fmaxf(z0, z1);
    #pragma unroll
    for (int o = 16; o; o >>= 1) m = fmaxf(m, __shfl_xor_sync(0xffffffffu, m, o));
    if ((tid & 31) == 0) red_a[tid >> 5] = m;
    __syncthreads();
    if (tid == 0) {
        float mm = red_a[0];
        #pragma unroll
        for (int i = 1; i < 8; ++i) mm = fmaxf(mm, red_a[i]);
        red_a[0] = mm;
    }
    __syncthreads();
    m = red_a[0];
    __syncthreads();
    e0 = __expf(z0 - m); e1 = __expf(z1 - m);
    s = e0 + e1;
    float d = e0 * Wfc[tid] + e1 * Wfc[tid + 256];
    #pragma unroll
    for (int o = 16; o; o >>= 1) {
        s += __shfl_xor_sync(0xffffffffu, s, o);
        d += __shfl_xor_sync(0xffffffffu, d, o);
    }
    if ((tid & 31) == 0) { red_a[tid >> 5] = s; red_b[tid >> 5] = d; }
    __syncthreads();
    if (tid == 0) {
        float ss = 0.f, dd = 0.f;
        #pragma unroll
        for (int i = 0; i < 8; ++i) { ss += red_a[i]; dd += red_b[i]; }
        out[b * TSTEPS + t + 1] = __fdividef(dd, ss) + bfc[0];
    }
}

// out[b, 0] = softmax_row(z[b]) . Wfc + bfc
__global__ __launch_bounds__(256) void softmaxdot_kernel(
    const float* __restrict__ Wfc, const float* __restrict__ bfc,
    float* __restrict__ out)
{
    const int b = blockIdx.x;
    const int tid = threadIdx.x;
    float v0 = g_z[b * HID + tid], v1 = g_z[b * HID + tid + 256];
    __shared__ float red_s[8], red_d[8];

    float m = fmaxf(v0, v1);
    #pragma unroll
    for (int o = 16; o; o >>= 1) m = fmaxf(m, __shfl_xor_sync(0xffffffffu, m, o));
    if ((tid & 31) == 0) red_s[tid >> 5] = m;
    __syncthreads();
    if (tid == 0) {
        float mm = red_s[0];
        #pragma unroll
        for (int i = 1; i < 8; ++i) mm = fmaxf(mm, red_s[i]);
        red_s[0] = mm;
    }
    __syncthreads();
    m = red_s[0];
    __syncthreads();
    float e0 = __expf(v0 - m), e1 = __expf(v1 - m);
    float s = e0 + e1;
    float d = e0 * Wfc[tid] + e1 * Wfc[tid + 256];
    #pragma unroll
    for (int o = 16; o; o >>= 1) {
        s += __shfl_xor_sync(0xffffffffu, s, o);
        d += __shfl_xor_sync(0xffffffffu, d, o);
    }
    if ((tid & 31) == 0) { red_s[tid >> 5] = s; red_d[tid >> 5] = d; }
    __syncthreads();
    if (tid == 0) {
        float ss = 0.f, dd = 0.f;
        #pragma unroll
        for (int i = 0; i < 8; ++i) { ss += red_s[i]; dd += red_d[i]; }
        out[b * TSTEPS + 0] = __fdividef(dd, ss) + bfc[0];
    }
}

// ---------------- launch -----------------------------------------------------
extern "C" void kernel_launch(void* const* d_in, const int* in_sizes, int n_in,
                              void* d_out, int out_size) {
    const float* y    = (const float*)d_in[0];
    const float* ts   = (const float*)d_in[1];
    const float* Wi   = (const float*)d_in[2];
    // d_in[3] = Wf — dead in the reference (f computed but unused), skipped.
    const float* Wg   = (const float*)d_in[4];
    const float* Wo   = (const float*)d_in[5];
    const float* Wout = (const float*)d_in[6];
    const float* bout = (const float*)d_in[7];
    const float* Wfc  = (const float*)d_in[8];
    const float* bfc  = (const float*)d_in[9];
    float* out = (float*)d_out;

    cudaFuncSetAttribute(fused_igo_mma, cudaFuncAttributeMaxDynamicSharedMemorySize, F_SMEM);
    cudaFuncSetAttribute(wout_mma,      cudaFuncAttributeMaxDynamicSharedMemorySize, W_SMEM);

    w2bf_kernel<<<(4 * HID * HID + 255) / 256, 256>>>(Wi, Wg, Wo, Wout);
    copy_z_kernel<<<(BATCH * HID + 255) / 256, 256>>>(y);
    softmaxdot_kernel<<<BATCH, 256>>>(Wfc, bfc, out);

    dim3 ggrid(BATCH / BM, HID / BN);   // 64 x 8
    for (int t = 0; t < TSTEPS - 1; ++t) {
        fused_igo_mma<<<ggrid, 256, F_SMEM>>>();
        wout_mma<<<ggrid, 256, W_SMEM>>>(bout);
        update_out_kernel<<<BATCH, 256>>>(ts, Wfc, bfc, out, t);
    }
}

// round 6
// speedup vs baseline: 1.1680x; 1.0089x over previous
#include <cuda_runtime.h>
#include <cuda_bf16.h>
#include <math.h>
#include <stdint.h>

#define HID    512
#define BATCH  4096
#define TSTEPS 20

#define BM 64
#define BN 64
#define BK 64
#define SK 72                           // padded smem row stride (bf16)
#define TILE_EL (64 * SK)               // 4608 el per 64x64 tile
#define F_STAGE_EL (4 * TILE_EL)        // A + Wi + Wg + Wo
#define F_SMEM (3 * F_STAGE_EL * 2)     // 110592 B (3-stage)
#define W_STAGE_EL (2 * TILE_EL)
#define W_SMEM (3 * W_STAGE_EL * 2)     // 55296 B (3-stage)

// ---------------- scratch ----------------------------------------------------
__device__ __align__(16) float          g_z  [BATCH * HID];
__device__ __align__(16) __nv_bfloat16  g_zb [BATCH * HID];
__device__ __align__(16) __nv_bfloat16  g_dhb[BATCH * HID];
__device__ __align__(16) float          g_s  [BATCH * HID];
__device__ __align__(16) __nv_bfloat16  g_wb [4][HID * HID];   // Wi, Wg, Wo, Wout

// ---------------- helpers ----------------------------------------------------
static __device__ __forceinline__ uint32_t smem_u32(const void* p) {
    uint32_t a;
    asm("{ .reg .u64 t; cvta.to.shared.u64 t, %1; cvt.u32.u64 %0, t; }" : "=r"(a) : "l"(p));
    return a;
}
#define CP16(dst, src) \
    asm volatile("cp.async.cg.shared.global [%0], [%1], 16;" :: "r"(dst), "l"(src))
#define CPC()  asm volatile("cp.async.commit_group;" ::: "memory")
#define CPW1() asm volatile("cp.async.wait_group 1;" ::: "memory")
#define CPW0() asm volatile("cp.async.wait_group 0;" ::: "memory")

__device__ __forceinline__ void ldm4(uint32_t a, uint32_t& r0, uint32_t& r1,
                                     uint32_t& r2, uint32_t& r3) {
    asm volatile("ldmatrix.sync.aligned.m8n8.x4.shared.b16 {%0,%1,%2,%3}, [%4];"
                 : "=r"(r0), "=r"(r1), "=r"(r2), "=r"(r3) : "r"(a));
}
__device__ __forceinline__ void mma16816(float* c, const uint32_t* a, uint32_t b0, uint32_t b1) {
    asm volatile("mma.sync.aligned.m16n8k16.row.col.f32.bf16.bf16.f32 "
                 "{%0,%1,%2,%3},{%4,%5,%6,%7},{%8,%9},{%0,%1,%2,%3};"
                 : "+f"(c[0]), "+f"(c[1]), "+f"(c[2]), "+f"(c[3])
                 : "r"(a[0]), "r"(a[1]), "r"(a[2]), "r"(a[3]), "r"(b0), "r"(b1));
}
__device__ __forceinline__ float fsig(float x)  { return __fdividef(1.f, 1.f + __expf(-x)); }
__device__ __forceinline__ float ftanh(float x) { return __fdividef(2.f, 1.f + __expf(-2.f * x)) - 1.f; }

// ---------------- setup ------------------------------------------------------
__global__ void w2bf_kernel(const float* __restrict__ Wi, const float* __restrict__ Wg,
                            const float* __restrict__ Wo, const float* __restrict__ Wout) {
    int i = blockIdx.x * blockDim.x + threadIdx.x;
    if (i >= 4 * HID * HID) return;
    int m = i >> 18, r = i & (HID * HID - 1);
    const float* src = (m == 0) ? Wi : (m == 1) ? Wg : (m == 2) ? Wo : Wout;
    g_wb[m][r] = __float2bfloat16_rn(src[r]);
}

__global__ void copy_z_kernel(const float* __restrict__ y) {
    int i = blockIdx.x * blockDim.x + threadIdx.x;
    if (i < BATCH * HID) { float v = y[i]; g_z[i] = v; g_zb[i] = __float2bfloat16_rn(v); }
}

// ---------------- cp.async issuers (stage in 0..2) ---------------------------
__device__ __forceinline__ void f_issue(uint32_t sb, int tid, int bm, int bn, int ch, int stage) {
    const uint32_t base = sb + (uint32_t)stage * (F_STAGE_EL * 2);
    const int k0 = ch * BK;
    #pragma unroll
    for (int i = 0; i < 8; ++i) {
        int idx = i * 256 + tid;              // 0..2047
        int tl = idx >> 9, r = (idx >> 3) & 63, c = idx & 7;
        const __nv_bfloat16* src = (tl == 0)
            ? (g_zb + (bm + r) * HID + k0 + c * 8)
            : (g_wb[tl - 1] + (bn + r) * HID + k0 + c * 8);
        uint32_t dst = base + (uint32_t)(tl * TILE_EL + r * SK + c * 8) * 2;
        CP16(dst, src);
    }
    CPC();
}
__device__ __forceinline__ void w_issue(uint32_t sb, int tid, int bm, int bn, int ch, int stage) {
    const uint32_t base = sb + (uint32_t)stage * (W_STAGE_EL * 2);
    const int k0 = ch * BK;
    #pragma unroll
    for (int i = 0; i < 4; ++i) {
        int idx = i * 256 + tid;              // 0..1023
        int tl = idx >> 9, r = (idx >> 3) & 63, c = idx & 7;
        const __nv_bfloat16* src = (tl == 0)
            ? (g_dhb + (bm + r) * HID + k0 + c * 8)
            : (g_wb[3] + (bn + r) * HID + k0 + c * 8);
        uint32_t dst = base + (uint32_t)(tl * TILE_EL + r * SK + c * 8) * 2;
        CP16(dst, src);
    }
    CPC();
}

// ---------------- fused i/g/o HMMA GEMM (64x64 tile, occ 2, 3-stage) ---------
// dh = sig(z@Wo^T) * tanh( sig(z@Wi^T) * tanh(z@Wg^T) ) -> g_dhb (bf16)
__global__ __launch_bounds__(256, 2) void fused_igo_mma() {
    extern __shared__ __nv_bfloat16 sm[];
    const uint32_t sb = smem_u32(sm);
    const int tid = threadIdx.x, lane = tid & 31, wid = tid >> 5;
    const int warpM = wid & 1, warpN = wid >> 1;      // 2 x 4 warps
    const int bm = blockIdx.x * BM, bn = blockIdx.y * BN;

    float acc[3][2][2][4];                            // [weight][mi][ni][4]
    #pragma unroll
    for (int w = 0; w < 3; ++w)
        #pragma unroll
        for (int mi = 0; mi < 2; ++mi)
            #pragma unroll
            for (int ni = 0; ni < 2; ++ni)
                #pragma unroll
                for (int q = 0; q < 4; ++q) acc[w][mi][ni][q] = 0.f;

    const int am = warpM * 32 + (lane & 15);
    const int ak = (lane >> 4) << 3;
    const int bnrow = warpN * 16 + ((lane >> 4) << 3) + (lane & 7);
    const int bk = ((lane >> 3) & 1) << 3;

    f_issue(sb, tid, bm, bn, 0, 0);
    f_issue(sb, tid, bm, bn, 1, 1);

    int stage = 0;
    #pragma unroll 1
    for (int ch = 0; ch < HID / BK; ++ch) {
        if (ch < HID / BK - 1) { CPW1(); } else { CPW0(); }
        __syncthreads();                               // single barrier per chunk
        if (ch + 2 < HID / BK) {
            int ns = stage + 2; if (ns >= 3) ns -= 3;
            f_issue(sb, tid, bm, bn, ch + 2, ns);      // stage disjoint from ch, ch+1
        }
        const uint32_t base = sb + (uint32_t)stage * (F_STAGE_EL * 2);
        #pragma unroll
        for (int kk = 0; kk < BK; kk += 16) {
            uint32_t fa[2][4];
            uint32_t aadr = base + (uint32_t)(am * SK + kk + ak) * 2;
            ldm4(aadr,               fa[0][0], fa[0][1], fa[0][2], fa[0][3]);
            ldm4(aadr + 16 * SK * 2, fa[1][0], fa[1][1], fa[1][2], fa[1][3]);
            const uint32_t boff = (uint32_t)(bnrow * SK + kk + bk) * 2;
            #pragma unroll
            for (int w = 0; w < 3; ++w) {
                uint32_t b0, b1, b2, b3;
                ldm4(base + (uint32_t)((w + 1) * TILE_EL) * 2 + boff, b0, b1, b2, b3);
                mma16816(acc[w][0][0], fa[0], b0, b1);
                mma16816(acc[w][0][1], fa[0], b2, b3);
                mma16816(acc[w][1][0], fa[1], b0, b1);
                mma16816(acc[w][1][1], fa[1], b2, b3);
            }
        }
        if (++stage >= 3) stage -= 3;
    }

    // epilogue: dh activation -> g_dhb
    #pragma unroll
    for (int mi = 0; mi < 2; ++mi) {
        const int r = bm + warpM * 32 + mi * 16 + (lane >> 2);
        #pragma unroll
        for (int ni = 0; ni < 2; ++ni) {
            const int col = bn + warpN * 16 + ni * 8 + ((lane & 3) << 1);
            float I0 = fsig(acc[0][mi][ni][0]), G0 = ftanh(acc[1][mi][ni][0]), O0 = fsig(acc[2][mi][ni][0]);
            float I1 = fsig(acc[0][mi][ni][1]), G1 = ftanh(acc[1][mi][ni][1]), O1 = fsig(acc[2][mi][ni][1]);
            float I2 = fsig(acc[0][mi][ni][2]), G2 = ftanh(acc[1][mi][ni][2]), O2 = fsig(acc[2][mi][ni][2]);
            float I3 = fsig(acc[0][mi][ni][3]), G3 = ftanh(acc[1][mi][ni][3]), O3 = fsig(acc[2][mi][ni][3]);
            *(__nv_bfloat162*)(g_dhb + r * HID + col) =
                __floats2bfloat162_rn(O0 * ftanh(I0 * G0), O1 * ftanh(I1 * G1));
            *(__nv_bfloat162*)(g_dhb + (r + 8) * HID + col) =
                __floats2bfloat162_rn(O2 * ftanh(I2 * G2), O3 * ftanh(I3 * G3));
        }
    }
}

// ---------------- Wout HMMA GEMM: s = dh @ Wout^T + bout (3-stage) -----------
__global__ __launch_bounds__(256, 3) void wout_mma(const float* __restrict__ bout) {
    extern __shared__ __nv_bfloat16 sm[];
    const uint32_t sb = smem_u32(sm);
    const int tid = threadIdx.x, lane = tid & 31, wid = tid >> 5;
    const int warpM = wid & 1, warpN = wid >> 1;
    const int bm = blockIdx.x * BM, bn = blockIdx.y * BN;

    float acc[2][2][4];
    #pragma unroll
    for (int mi = 0; mi < 2; ++mi)
        #pragma unroll
        for (int ni = 0; ni < 2; ++ni)
            #pragma unroll
            for (int q = 0; q < 4; ++q) acc[mi][ni][q] = 0.f;

    const int am = warpM * 32 + (lane & 15);
    const int ak = (lane >> 4) << 3;
    const int bnrow = warpN * 16 + ((lane >> 4) << 3) + (lane & 7);
    const int bk = ((lane >> 3) & 1) << 3;

    w_issue(sb, tid, bm, bn, 0, 0);
    w_issue(sb, tid, bm, bn, 1, 1);

    int stage = 0;
    #pragma unroll 1
    for (int ch = 0; ch < HID / BK; ++ch) {
        if (ch < HID / BK - 1) { CPW1(); } else { CPW0(); }
        __syncthreads();
        if (ch + 2 < HID / BK) {
            int ns = stage + 2; if (ns >= 3) ns -= 3;
            w_issue(sb, tid, bm, bn, ch + 2, ns);
        }
        const uint32_t base = sb + (uint32_t)stage * (W_STAGE_EL * 2);
        #pragma unroll
        for (int kk = 0; kk < BK; kk += 16) {
            uint32_t fa[2][4], b0, b1, b2, b3;
            uint32_t aadr = base + (uint32_t)(am * SK + kk + ak) * 2;
            ldm4(aadr,               fa[0][0], fa[0][1], fa[0][2], fa[0][3]);
            ldm4(aadr + 16 * SK * 2, fa[1][0], fa[1][1], fa[1][2], fa[1][3]);
            ldm4(base + (uint32_t)(TILE_EL) * 2 + (uint32_t)(bnrow * SK + kk + bk) * 2,
                 b0, b1, b2, b3);
            mma16816(acc[0][0], fa[0], b0, b1);
            mma16816(acc[0][1], fa[0], b2, b3);
            mma16816(acc[1][0], fa[1], b0, b1);
            mma16816(acc[1][1], fa[1], b2, b3);
        }
        if (++stage >= 3) stage -= 3;
    }

    #pragma unroll
    for (int mi = 0; mi < 2; ++mi) {
        const int r = bm + warpM * 32 + mi * 16 + (lane >> 2);
        #pragma unroll
        for (int ni = 0; ni < 2; ++ni) {
            const int col = bn + warpN * 16 + ni * 8 + ((lane & 3) << 1);
            float b0v = bout[col], b1v = bout[col + 1];
            float2 lo = { acc[mi][ni][0] + b0v, acc[mi][ni][1] + b1v };
            float2 hi = { acc[mi][ni][2] + b0v, acc[mi][ni][3] + b1v };
            *(float2*)(g_s + r * HID + col)       = lo;
            *(float2*)(g_s + (r + 8) * HID + col) = hi;
        }
    }
}

// ---------------- fused softmax(s)->z update + softmax(z)->out[t+1] ----------
__global__ __launch_bounds__(256) void update_out_kernel(
    const float* __restrict__ ts, const float* __restrict__ Wfc,
    const float* __restrict__ bfc, float* __restrict__ out, int t)
{
    const int b = blockIdx.x;
    const int tid = threadIdx.x;
    __shared__ float red_a[8], red_b[8];

    float v0 = g_s[b * HID + tid], v1 = g_s[b * HID + tid + 256];
    float m = fmaxf(v0, v1);
    #pragma unroll
    for (int o = 16; o; o >>= 1) m = fmaxf(m, __shfl_xor_sync(0xffffffffu, m, o));
    if ((tid & 31) == 0) red_a[tid >> 5] = m;
    __syncthreads();
    if (tid == 0) {
        float mm = red_a[0];
        #pragma unroll
        for (int i = 1; i < 8; ++i) mm = fmaxf(mm, red_a[i]);
        red_a[0] = mm;
    }
    __syncthreads();
    m = red_a[0];
    __syncthreads();
    float e0 = __expf(v0 - m), e1 = __expf(v1 - m);
    float s = e0 + e1;
    #pragma unroll
    for (int o = 16; o; o >>= 1) s += __shfl_xor_sync(0xffffffffu, s, o);
    if ((tid & 31) == 0) red_a[tid >> 5] = s;
    __syncthreads();
    if (tid == 0) {
        float ss = 0.f;
        #pragma unroll
        for (int i = 0; i < 8; ++i) ss += red_a[i];
        red_a[0] = ss;
    }
    __syncthreads();
    float dt = ts[t + 1] - ts[t];
    float inv = __fdividef(dt, red_a[0]);
    float z0 = g_z[b * HID + tid      ] + e0 * inv;
    float z1 = g_z[b * HID + tid + 256] + e1 * inv;
    g_z[b * HID + tid      ] = z0;
    g_z[b * HID + tid + 256] = z1;
    g_zb[b * HID + tid      ] = __float2bfloat16_rn(z0);
    g_zb[b * HID + tid + 256] = __float2bfloat16_rn(z1);
    __syncthreads();

    m = fmaxf(z0, z1);
    #pragma unroll
    for (int o = 16; o; o >>= 1) m = fmaxf(m, __shfl_xor_sync(0xffffffffu, m, o));
    if ((tid & 31) == 0) red_a[tid >> 5] = m;
    __syncthreads();
    if (tid == 0) {
        float mm = red_a[0];
        #pragma unroll
        for (int i = 1; i < 8; ++i) mm = fmaxf(mm, red_a[i]);
        red_a[0] = mm;
    }
    __syncthreads();
    m = red_a[0];
    __syncthreads();
    e0 = __expf(z0 - m); e1 = __expf(z1 - m);
    s = e0 + e1;
    float d = e0 * Wfc[tid] + e1 * Wfc[tid + 256];
    #pragma unroll
    for (int o = 16; o; o >>= 1) {
        s += __shfl_xor_sync(0xffffffffu, s, o);
        d += __shfl_xor_sync(0xffffffffu, d, o);
    }
    if ((tid & 31) == 0) { red_a[tid >> 5] = s; red_b[tid >> 5] = d; }
    __syncthreads();
    if (tid == 0) {
        float ss = 0.f, dd = 0.f;
        #pragma unroll
        for (int i = 0; i < 8; ++i) { ss += red_a[i]; dd += red_b[i]; }
        out[b * TSTEPS + t + 1] = __fdividef(dd, ss) + bfc[0];
    }
}

// out[b, 0] = softmax_row(z[b]) . Wfc + bfc
__global__ __launch_bounds__(256) void softmaxdot_kernel(
    const float* __restrict__ Wfc, const float* __restrict__ bfc,
    float* __restrict__ out)
{
    const int b = blockIdx.x;
    const int tid = threadIdx.x;
    float v0 = g_z[b * HID + tid], v1 = g_z[b * HID + tid + 256];
    __shared__ float red_s[8], red_d[8];

    float m = fmaxf(v0, v1);
    #pragma unroll
    for (int o = 16; o; o >>= 1) m = fmaxf(m, __shfl_xor_sync(0xffffffffu, m, o));
    if ((tid & 31) == 0) red_s[tid >> 5] = m;
    __syncthreads();
    if (tid == 0) {
        float mm = red_s[0];
        #pragma unroll
        for (int i = 1; i < 8; ++i) mm = fmaxf(mm, red_s[i]);
        red_s[0] = mm;
    }
    __syncthreads();
    m = red_s[0];
    __syncthreads();
    float e0 = __expf(v0 - m), e1 = __expf(v1 - m);
    float s = e0 + e1;
    float d = e0 * Wfc[tid] + e1 * Wfc[tid + 256];
    #pragma unroll
    for (int o = 16; o; o >>= 1) {
        s += __shfl_xor_sync(0xffffffffu, s, o);
        d += __shfl_xor_sync(0xffffffffu, d, o);
    }
    if ((tid & 31) == 0) { red_s[tid >> 5] = s; red_d[tid >> 5] = d; }
    __syncthreads();
    if (tid == 0) {
        float ss = 0.f, dd = 0.f;
        #pragma unroll
        for (int i = 0; i < 8; ++i) { ss += red_s[i]; dd += red_d[i]; }
        out[b * TSTEPS + 0] = __fdividef(dd, ss) + bfc[0];
    }
}

// ---------------- launch -----------------------------------------------------
extern "C" void kernel_launch(void* const* d_in, const int* in_sizes, int n_in,
                              void* d_out, int out_size) {
    const float* y    = (const float*)d_in[0];
    const float* ts   = (const float*)d_in[1];
    const float* Wi   = (const float*)d_in[2];
    // d_in[3] = Wf — dead in the reference (f computed but unused), skipped.
    const float* Wg   = (const float*)d_in[4];
    const float* Wo   = (const float*)d_in[5];
    const float* Wout = (const float*)d_in[6];
    const float* bout = (const float*)d_in[7];
    const float* Wfc  = (const float*)d_in[8];
    const float* bfc  = (const float*)d_in[9];
    float* out = (float*)d_out;

    cudaFuncSetAttribute(fused_igo_mma, cudaFuncAttributeMaxDynamicSharedMemorySize, F_SMEM);
    cudaFuncSetAttribute(wout_mma,      cudaFuncAttributeMaxDynamicSharedMemorySize, W_SMEM);

    w2bf_kernel<<<(4 * HID * HID + 255) / 256, 256>>>(Wi, Wg, Wo, Wout);
    copy_z_kernel<<<(BATCH * HID + 255) / 256, 256>>>(y);
    softmaxdot_kernel<<<BATCH, 256>>>(Wfc, bfc, out);

    dim3 ggrid(BATCH / BM, HID / BN);   // 64 x 8
    for (int t = 0; t < TSTEPS - 1; ++t) {
        fused_igo_mma<<<ggrid, 256, F_SMEM>>>();
        wout_mma<<<ggrid, 256, W_SMEM>>>(bout);
        update_out_kernel<<<BATCH, 256>>>(ts, Wfc, bfc, out, t);
    }
}